// round 1
// baseline (speedup 1.0000x reference)
#include <cuda_runtime.h>

// Output: R[b, s, d, d] with B=16, S=1024, D=64 (fp32).
// Per (b,s): 32 2x2 rotation blocks on the diagonal, zeros elsewhere.
//   row r (even), h = r/2:  R[r, r] = cos, R[r, r+1] = -sin
//   row r+1 (odd):          R[r+1, r] = sin, R[r+1, r+1] = cos
// angle = spa_feat[b, s, ch] * inv_freq[i], ch = h/16, i = h%16,
// inv_freq[i] = 10000^(-i/16).
//
// One thread per aligned float4 of the output (the nonzero pair always
// fits inside one float4). Fully coalesced 128-bit stores; pure HBM-bound.

static __device__ __forceinline__ float inv_freq_of(unsigned i) {
    // 10000^(-i/16) = 2^(-i * log2(10000)/16)
    const float K = 13.287712379549449f / 16.0f;
    return exp2f(-(float)i * K);
}

__global__ void __launch_bounds__(256) rope2d_R_kernel(
    const float* __restrict__ spa,   // (B*S, 2)
    float4* __restrict__ out)        // (B*S, 64, 16) float4 view
{
    unsigned g = blockIdx.x * blockDim.x + threadIdx.x;   // < 16,777,216 exactly
    unsigned bs     = g >> 10;        // matrix index (1024 float4 per matrix)
    unsigned within = g & 1023u;
    unsigned row    = within >> 4;    // 0..63
    unsigned f4     = within & 15u;   // float4 column index 0..15

    float4 v = make_float4(0.f, 0.f, 0.f, 0.f);

    unsigned r0 = row & ~1u;          // even base row of the 2x2 block
    if ((r0 >> 2) == f4) {            // this float4 holds the nonzero pair
        unsigned h  = row >> 1;       // 0..31
        unsigned ch = h >> 4;         // 0 = x, 1 = y
        unsigned i  = h & 15u;
        float angle = spa[bs * 2u + ch] * inv_freq_of(i);
        float s, c;
        sincosf(angle, &s, &c);
        float a, b;
        if (row & 1u) { a = s; b = c; }     // odd row: (sin, cos)
        else          { a = c; b = -s; }    // even row: (cos, -sin)
        if (r0 & 2u)  { v.z = a; v.w = b; } // pair at lanes 2,3
        else          { v.x = a; v.y = b; } // pair at lanes 0,1
    }

    out[g] = v;
}

extern "C" void kernel_launch(void* const* d_in, const int* in_sizes, int n_in,
                              void* d_out, int out_size)
{
    const float* spa = (const float*)d_in[0];
    float4* out = (float4*)d_out;

    // out_size = 16*1024*64*64 = 67,108,864 floats = 16,777,216 float4
    unsigned n_f4 = (unsigned)(out_size / 4);
    unsigned threads = 256;
    unsigned blocks = n_f4 / threads;   // 65536, exact
    rope2d_R_kernel<<<blocks, threads>>>(spa, out);
}

// round 2
// speedup vs baseline: 1.7046x; 1.7046x over previous
#include <cuda_runtime.h>
#include <cstdint>

// Output: R[b, s, 64, 64] fp32, B*S = 16384 matrices of 16 KB each.
// Per matrix: 32 2x2 rotation blocks on the diagonal, zeros elsewhere.
//
// Strategy: one CTA per matrix. Build the full 16 KB matrix in SMEM
// (mostly zeros + 128 sin/cos values), then stream it to GMEM with a
// single cp.async.bulk (TMA bulk store). This removes the per-byte SM
// instruction overhead that capped the previous kernel at ~4.3 TB/s.

static __device__ __forceinline__ float inv_freq_of(unsigned i) {
    // 10000^(-i/16) = 2^(-i * log2(10000)/16)
    const float K = 13.287712379549449f / 16.0f;
    return exp2f(-(float)i * K);
}

__global__ void __launch_bounds__(256) rope2d_tma_kernel(
    const float* __restrict__ spa,   // (B*S, 2)
    float* __restrict__ out)         // (B*S, 64, 64)
{
    __shared__ alignas(128) float4 tile[1024];   // 16 KB = one matrix

    unsigned bs = blockIdx.x;
    // Broadcast loads (all threads same address -> L1 broadcast)
    float x = __ldg(&spa[bs * 2u + 0]);
    float y = __ldg(&spa[bs * 2u + 1]);

    // Fill SMEM: 1024 float4 slots, 4 per thread.
    #pragma unroll
    for (unsigned k = 0; k < 4; k++) {
        unsigned w   = threadIdx.x + k * 256u;   // 0..1023
        unsigned row = w >> 4;                   // 0..63
        unsigned f4  = w & 15u;                  // float4 col 0..15

        float4 v = make_float4(0.f, 0.f, 0.f, 0.f);
        unsigned r0 = row & ~1u;                 // even base row of 2x2 block
        if ((r0 >> 2) == f4) {                   // this float4 holds the pair
            unsigned h  = row >> 1;              // 0..31
            float coord = (h & 16u) ? y : x;     // ch = h/16
            unsigned i  = h & 15u;
            float s, c;
            sincosf(coord * inv_freq_of(i), &s, &c);
            float a, b;
            if (row & 1u) { a = s; b = c;  }     // odd row: (sin, cos)
            else          { a = c; b = -s; }     // even row: (cos, -sin)
            if (r0 & 2u)  { v.z = a; v.w = b; }
            else          { v.x = a; v.y = b; }
        }
        tile[w] = v;
    }
    __syncthreads();

    if (threadIdx.x == 0) {
        uint32_t saddr;
        asm("{ .reg .u64 t; cvta.to.shared.u64 t, %1; cvt.u32.u64 %0, t; }"
            : "=r"(saddr) : "l"(tile));
        // Order generic-proxy SMEM writes before the async-proxy bulk copy.
        asm volatile("fence.proxy.async.shared::cta;" ::: "memory");
        asm volatile(
            "cp.async.bulk.global.shared::cta.bulk_group [%0], [%1], %2;"
            :: "l"(out + (size_t)bs * 4096u), "r"(saddr), "r"(16384u)
            : "memory");
        asm volatile("cp.async.bulk.commit_group;" ::: "memory");
        asm volatile("cp.async.bulk.wait_group 0;" ::: "memory");
    }
}

extern "C" void kernel_launch(void* const* d_in, const int* in_sizes, int n_in,
                              void* d_out, int out_size)
{
    const float* spa = (const float*)d_in[0];
    float* out = (float*)d_out;

    unsigned n_mat = (unsigned)(out_size / 4096);   // 16384 matrices
    rope2d_tma_kernel<<<n_mat, 256>>>(spa, out);
}